// round 4
// baseline (speedup 1.0000x reference)
#include <cuda_runtime.h>
#include <stdint.h>

#define NROWS 500000
#define WPB   8
#define TPB   (WPB * 32)

__global__ __launch_bounds__(TPB)
void vns_kernel(const float* __restrict__ x, float* __restrict__ out) {
    const int lane = threadIdx.x & 31;
    const int row  = blockIdx.x * WPB + (threadIdx.x >> 5);   // grid exact: no bound check

    // ---- lane holds vectors 2*lane (v0..v2) and 2*lane+1 (v3..v5) ----
    const float2* src = (const float2*)(x + (size_t)row * 192) + 3 * lane;
    float2 p0 = src[0];
    float2 p1 = src[1];
    float2 p2 = src[2];
    float v0 = p0.x, v1 = p0.y, v2 = p1.x;
    float v3 = p1.y, v4 = p2.x, v5 = p2.y;

    // ---- squared norms, bit-matching ((a*a + b*b) + c*c) ----
    float n0 = __fadd_rn(__fadd_rn(__fmul_rn(v0, v0), __fmul_rn(v1, v1)), __fmul_rn(v2, v2));
    float n1 = __fadd_rn(__fadd_rn(__fmul_rn(v3, v3), __fmul_rn(v4, v4)), __fmul_rn(v5, v5));

    // ---- 32-bit keys: truncated norm (26 bits) | (63 - idx) (6 bits, distinct) ----
    unsigned K0 = (__float_as_uint(n0) & 0xFFFFFFC0u) | (unsigned)(63 - 2 * lane);
    unsigned K1 = (__float_as_uint(n1) & 0xFFFFFFC0u) | (unsigned)(62 - 2 * lane);

    // ---- full bitonic sort-64 DESC, interleaved layout (elem 2l+r in lane l reg r) ----
    #pragma unroll
    for (int k = 2; k <= 64; k <<= 1) {
        #pragma unroll
        for (int j = k >> 1; j > 0; j >>= 1) {
            bool dirTop = ((lane & (k >> 1)) == 0);     // ((2l+r) & k) == 0, k >= 2
            if (j == 1) {
                // in-lane CE: reg0 is the low position
                unsigned hi = max(K0, K1), lo = min(K0, K1);
                K0 = dirTop ? hi : lo;
                K1 = dirTop ? lo : hi;
            } else {
                int lj = j >> 1;
                unsigned q0 = __shfl_xor_sync(0xffffffffu, K0, lj);
                unsigned q1 = __shfl_xor_sync(0xffffffffu, K1, lj);
                bool keep = (dirTop == ((lane & lj) == 0));
                K0 = keep ? max(K0, q0) : min(K0, q0);
                K1 = keep ? max(K1, q1) : min(K1, q1);
            }
        }
    }
    // Sorted desc: position p = 2*lane + r.

    // ---- collision check: adjacent truncated-norm-equal among positions 0..16 ----
    unsigned nk0 = __shfl_down_sync(0xffffffffu, K0, 1);   // key at position 2l+2
    bool bad = (lane < 8) &&
               ((((K0 ^ K1) >> 6) == 0) || (((K1 ^ nk0) >> 6) == 0));
    bool anyBad = __ballot_sync(0xffffffffu, bad) != 0;

    float* dst = out + (size_t)row * 48;

    if (!anyBad) {
        // ---- fast path: lane p<16 emits sorted position p ----
        unsigned Ka = __shfl_sync(0xffffffffu, K0, lane >> 1);
        unsigned Kb = __shfl_sync(0xffffffffu, K1, lane >> 1);
        unsigned Kp = (lane & 1) ? Kb : Ka;
        int idx  = 63 - (int)(Kp & 63u);
        int srcl = idx >> 1;
        float a0 = __shfl_sync(0xffffffffu, v0, srcl);
        float a1 = __shfl_sync(0xffffffffu, v1, srcl);
        float a2 = __shfl_sync(0xffffffffu, v2, srcl);
        float b0 = __shfl_sync(0xffffffffu, v3, srcl);
        float b1 = __shfl_sync(0xffffffffu, v4, srcl);
        float b2 = __shfl_sync(0xffffffffu, v5, srcl);
        if (lane < 16) {
            bool oddv = (idx & 1);
            dst[3 * lane + 0] = oddv ? b0 : a0;
            dst[3 * lane + 1] = oddv ? b1 : a1;
            dst[3 * lane + 2] = oddv ? b2 : a2;
        }
    } else {
        // ---- exact fallback (rare, warp-uniform): same network, 64-bit keys ----
        unsigned long long A0 = ((unsigned long long)__float_as_uint(n0) << 32) | (unsigned)(63 - 2 * lane);
        unsigned long long A1 = ((unsigned long long)__float_as_uint(n1) << 32) | (unsigned)(62 - 2 * lane);
        #pragma unroll
        for (int k = 2; k <= 64; k <<= 1) {
            #pragma unroll
            for (int j = k >> 1; j > 0; j >>= 1) {
                bool dirTop = ((lane & (k >> 1)) == 0);
                if (j == 1) {
                    unsigned long long hi = (A0 > A1) ? A0 : A1;
                    unsigned long long lo = (A0 > A1) ? A1 : A0;
                    A0 = dirTop ? hi : lo;
                    A1 = dirTop ? lo : hi;
                } else {
                    int lj = j >> 1;
                    unsigned long long q0 = __shfl_xor_sync(0xffffffffu, A0, lj);
                    unsigned long long q1 = __shfl_xor_sync(0xffffffffu, A1, lj);
                    bool keep = (dirTop == ((lane & lj) == 0));
                    A0 = keep ? ((A0 > q0) ? A0 : q0) : ((A0 > q0) ? q0 : A0);
                    A1 = keep ? ((A1 > q1) ? A1 : q1) : ((A1 > q1) ? q1 : A1);
                }
            }
        }
        unsigned long long Ka = __shfl_sync(0xffffffffu, A0, lane >> 1);
        unsigned long long Kb = __shfl_sync(0xffffffffu, A1, lane >> 1);
        unsigned long long Kp = (lane & 1) ? Kb : Ka;
        int idx  = 63 - (int)(Kp & 63ull);
        int srcl = idx >> 1;
        float a0 = __shfl_sync(0xffffffffu, v0, srcl);
        float a1 = __shfl_sync(0xffffffffu, v1, srcl);
        float a2 = __shfl_sync(0xffffffffu, v2, srcl);
        float b0 = __shfl_sync(0xffffffffu, v3, srcl);
        float b1 = __shfl_sync(0xffffffffu, v4, srcl);
        float b2 = __shfl_sync(0xffffffffu, v5, srcl);
        if (lane < 16) {
            bool oddv = (idx & 1);
            dst[3 * lane + 0] = oddv ? b0 : a0;
            dst[3 * lane + 1] = oddv ? b1 : a1;
            dst[3 * lane + 2] = oddv ? b2 : a2;
        }
    }
}

extern "C" void kernel_launch(void* const* d_in, const int* in_sizes, int n_in,
                              void* d_out, int out_size) {
    const float* x = (const float*)d_in[0];
    float* out = (float*)d_out;
    vns_kernel<<<NROWS / WPB, TPB>>>(x, out);
}

// round 5
// speedup vs baseline: 1.2262x; 1.2262x over previous
#include <cuda_runtime.h>
#include <stdint.h>

#define NROWS 500000
#define WPB   8
#define TPB   (WPB * 32)
#define ROWS_PER_BLOCK (WPB * 2)

template<class T> __device__ __forceinline__ T vmax(T a, T b) { return a > b ? a : b; }
template<class T> __device__ __forceinline__ T vmin(T a, T b) { return a < b ? a : b; }

template<class T>
__device__ __forceinline__ void ce_cross(T K[4], int lj, bool keep, unsigned m) {
    #pragma unroll
    for (int r = 0; r < 4; r++) {
        T q = __shfl_xor_sync(m, K[r], lj);
        K[r] = keep ? vmax(K[r], q) : vmin(K[r], q);
    }
}
template<class T>
__device__ __forceinline__ void ce_j2(T K[4], bool d) {   // pairs (0,2),(1,3), low regs 0,1
    T h0 = vmax(K[0], K[2]), l0 = vmin(K[0], K[2]);
    K[0] = d ? h0 : l0;  K[2] = d ? l0 : h0;
    T h1 = vmax(K[1], K[3]), l1 = vmin(K[1], K[3]);
    K[1] = d ? h1 : l1;  K[3] = d ? l1 : h1;
}
template<class T>
__device__ __forceinline__ void ce_j1(T K[4], bool dA, bool dB) { // pairs (0,1),(2,3)
    T h0 = vmax(K[0], K[1]), l0 = vmin(K[0], K[1]);
    K[0] = dA ? h0 : l0;  K[1] = dA ? l0 : h0;
    T h1 = vmax(K[2], K[3]), l1 = vmin(K[2], K[3]);
    K[2] = dB ? h1 : l1;  K[3] = dB ? l1 : h1;
}

// Full bitonic sort-64 DESC; element e = 4*s + r lives in lane (s within 16-group), reg r.
template<class T>
__device__ __forceinline__ void sort64(T K[4], const int s, const unsigned m) {
    // k=2 (dir per reg-pair: compile-time)
    ce_j1(K, true, false);
    // k=4
    { bool d = ((s & 1) == 0); ce_j2(K, d); ce_j1(K, d, d); }
    // k=8
    { bool d = ((s & 2) == 0);
      ce_cross(K, 1, d == ((s & 1) == 0), m);
      ce_j2(K, d); ce_j1(K, d, d); }
    // k=16
    { bool d = ((s & 4) == 0);
      ce_cross(K, 2, d == ((s & 2) == 0), m);
      ce_cross(K, 1, d == ((s & 1) == 0), m);
      ce_j2(K, d); ce_j1(K, d, d); }
    // k=32
    { bool d = ((s & 8) == 0);
      ce_cross(K, 4, d == ((s & 4) == 0), m);
      ce_cross(K, 2, d == ((s & 2) == 0), m);
      ce_cross(K, 1, d == ((s & 1) == 0), m);
      ce_j2(K, d); ce_j1(K, d, d); }
    // k=64 (dirTop always true: e < 64)
    ce_cross(K, 8, ((s & 8) == 0), m);
    ce_cross(K, 4, ((s & 4) == 0), m);
    ce_cross(K, 2, ((s & 2) == 0), m);
    ce_cross(K, 1, ((s & 1) == 0), m);
    ce_j2(K, true); ce_j1(K, true, true);
}

__global__ __launch_bounds__(TPB)
void vns_kernel(const float* __restrict__ x, float* __restrict__ out) {
    const int lane = threadIdx.x & 31;
    const int s    = lane & 15;                       // sublane within half-warp
    const int warp = threadIdx.x >> 5;
    const int row  = blockIdx.x * ROWS_PER_BLOCK + warp * 2 + (lane >> 4);
    const unsigned hm = 0xFFFFu << (lane & 16);       // half-warp mask

    // ---- load: lane holds elements 4s..4s+3 = floats [12s, 12s+12) : 3 x float4 ----
    const float* __restrict__ xrow = x + (size_t)row * 192;
    const float4* p4 = (const float4*)xrow + 3 * s;
    float4 a = p4[0], b = p4[1], c = p4[2];

    // ---- squared norms, bit-matching ((x*x + y*y) + z*z) ----
    float n0 = __fadd_rn(__fadd_rn(__fmul_rn(a.x, a.x), __fmul_rn(a.y, a.y)), __fmul_rn(a.z, a.z));
    float n1 = __fadd_rn(__fadd_rn(__fmul_rn(a.w, a.w), __fmul_rn(b.x, b.x)), __fmul_rn(b.y, b.y));
    float n2 = __fadd_rn(__fadd_rn(__fmul_rn(b.z, b.z), __fmul_rn(b.w, b.w)), __fmul_rn(c.x, c.x));
    float n3 = __fadd_rn(__fadd_rn(__fmul_rn(c.y, c.y), __fmul_rn(c.z, c.z)), __fmul_rn(c.w, c.w));

    // ---- 32-bit keys: truncated norm (26 bits) | (63 - idx) (6 bits, distinct) ----
    const unsigned base63 = 63 - 4 * s;
    unsigned K[4];
    K[0] = (__float_as_uint(n0) & 0xFFFFFFC0u) | (base63    );
    K[1] = (__float_as_uint(n1) & 0xFFFFFFC0u) | (base63 - 1);
    K[2] = (__float_as_uint(n2) & 0xFFFFFFC0u) | (base63 - 2);
    K[3] = (__float_as_uint(n3) & 0xFFFFFFC0u) | (base63 - 3);

    sort64(K, s, 0xffffffffu);
    // sorted DESC: position p = 4s + r within each half-warp.

    // ---- tie check: adjacent truncated-equal among sorted positions 0..16 ----
    unsigned nk0 = __shfl_down_sync(0xffffffffu, K[0], 1);   // next lane's pos 4s+4
    bool bad = (s <= 3) &&
               ((((K[0] ^ K[1]) >> 6) == 0) ||
                (((K[1] ^ K[2]) >> 6) == 0) ||
                (((K[2] ^ K[3]) >> 6) == 0) ||
                (((K[3] ^ nk0 ) >> 6) == 0));
    unsigned bal = __ballot_sync(0xffffffffu, bad);
    bool myHalfBad = ((bal >> (lane & 16)) & 0xFFFFu) != 0;

    float* __restrict__ orow = out + (size_t)row * 48;

    if (!myHalfBad) {
        // ---- fast path: sublane s emits sorted position s (s < 16 always) ----
        int srcl = (lane & 16) | (s >> 2);
        unsigned ka = __shfl_sync(hm, K[0], srcl);
        unsigned kb = __shfl_sync(hm, K[1], srcl);
        unsigned kc = __shfl_sync(hm, K[2], srcl);
        unsigned kd = __shfl_sync(hm, K[3], srcl);
        unsigned t0 = (s & 1) ? kb : ka;
        unsigned t1 = (s & 1) ? kd : kc;
        unsigned Kp = (s & 2) ? t1 : t0;
        int idx = 63 - (int)(Kp & 63u);
        const float* v = xrow + 3 * idx;                 // L1-resident re-read
        orow[3 * s + 0] = v[0];
        orow[3 * s + 1] = v[1];
        orow[3 * s + 2] = v[2];
    } else {
        // ---- exact fallback (rare, per-half-warp uniform): 64-bit keys, same network ----
        unsigned long long A[4];
        A[0] = ((unsigned long long)__float_as_uint(n0) << 32) | (base63    );
        A[1] = ((unsigned long long)__float_as_uint(n1) << 32) | (base63 - 1);
        A[2] = ((unsigned long long)__float_as_uint(n2) << 32) | (base63 - 2);
        A[3] = ((unsigned long long)__float_as_uint(n3) << 32) | (base63 - 3);
        sort64(A, s, hm);
        int srcl = (lane & 16) | (s >> 2);
        unsigned long long ka = __shfl_sync(hm, A[0], srcl);
        unsigned long long kb = __shfl_sync(hm, A[1], srcl);
        unsigned long long kc = __shfl_sync(hm, A[2], srcl);
        unsigned long long kd = __shfl_sync(hm, A[3], srcl);
        unsigned long long t0 = (s & 1) ? kb : ka;
        unsigned long long t1 = (s & 1) ? kd : kc;
        unsigned long long Kp = (s & 2) ? t1 : t0;
        int idx = 63 - (int)(Kp & 63ull);
        const float* v = xrow + 3 * idx;
        orow[3 * s + 0] = v[0];
        orow[3 * s + 1] = v[1];
        orow[3 * s + 2] = v[2];
    }
}

extern "C" void kernel_launch(void* const* d_in, const int* in_sizes, int n_in,
                              void* d_out, int out_size) {
    const float* x = (const float*)d_in[0];
    float* out = (float*)d_out;
    vns_kernel<<<NROWS / ROWS_PER_BLOCK, TPB>>>(x, out);
}

// round 6
// speedup vs baseline: 1.5134x; 1.2342x over previous
#include <cuda_runtime.h>
#include <stdint.h>

#define NROWS 500000
#define WPB   8
#define TPB   (WPB * 32)
#define ROWS_PER_BLOCK (WPB * 2)

template<class T> __device__ __forceinline__ T vmax(T a, T b) { return a > b ? a : b; }
template<class T> __device__ __forceinline__ T vmin(T a, T b) { return a < b ? a : b; }

// fixed-direction CE: low reg keeps max (descending)
template<class T> __device__ __forceinline__ void ceF(T& a, T& b) {
    T h = vmax(a, b), l = vmin(a, b); a = h; b = l;
}
// in-lane bitonic-4 sort (input bitonic, output descending)
template<class T> __device__ __forceinline__ void bit4(T K[4]) {
    ceF(K[0], K[2]); ceF(K[1], K[3]);
    ceF(K[0], K[1]); ceF(K[2], K[3]);
}
// cross-lane straight CE at distance d: keep max if km
template<class T> __device__ __forceinline__ void crossK(T K[4], int d, bool km, unsigned m) {
    #pragma unroll
    for (int r = 0; r < 4; r++) {
        T q = __shfl_xor_sync(m, K[r], d);
        K[r] = km ? vmax(K[r], q) : vmin(K[r], q);
    }
}
// cross-lane reversed CE: K[r] vs partner's K[3-r]; keep max if km
template<class T> __device__ __forceinline__ void crossRev(T K[4], int d, bool km, unsigned m) {
    T q0 = __shfl_xor_sync(m, K[3], d);
    T q1 = __shfl_xor_sync(m, K[2], d);
    T q2 = __shfl_xor_sync(m, K[1], d);
    T q3 = __shfl_xor_sync(m, K[0], d);
    K[0] = km ? vmax(K[0], q0) : vmin(K[0], q0);
    K[1] = km ? vmax(K[1], q1) : vmin(K[1], q1);
    K[2] = km ? vmax(K[2], q2) : vmin(K[2], q2);
    K[3] = km ? vmax(K[3], q3) : vmin(K[3], q3);
}

// Top-16-of-64 sorted DESC. Input: lane (s=lane&15) holds elements 4s..4s+3 in K[0..3].
// Output: every 4-lane group holds the sorted top-16; position p = 4*(s&3) + r.
template<class T>
__device__ __forceinline__ void top16(T K[4], bool P1, bool P2, unsigned m) {
    // in-lane sort-4 desc (all compile-time)
    ceF(K[0], K[1]); ceF(K[2], K[3]);
    ceF(K[0], K[2]); ceF(K[1], K[3]);
    ceF(K[1], K[2]);
    // merge lane pairs -> sorted-8 (even lane = top half)
    crossRev(K, 1, P1, m);
    bit4(K);
    // merge -> sorted-16 per 4-lane group
    crossRev(K, 3, P2, m);
    crossK(K, 1, P1, m);
    bit4(K);
    // merge two sorted-16s across xor4, prune to top-16 (keep max both sides), re-sort
    crossRev(K, 7, true, m);
    crossK(K, 2, P2, m);
    crossK(K, 1, P1, m);
    bit4(K);
    // same across xor8 -> top-16 of 64
    crossRev(K, 11, true, m);
    crossK(K, 2, P2, m);
    crossK(K, 1, P1, m);
    bit4(K);
}

__global__ __launch_bounds__(TPB)
void vns_kernel(const float* __restrict__ x, float* __restrict__ out) {
    const int lane = threadIdx.x & 31;
    const int sh   = lane & 15;                       // sublane within half-warp (row)
    const int row  = blockIdx.x * ROWS_PER_BLOCK + (threadIdx.x >> 5) * 2 + (lane >> 4);
    const unsigned hm = 0xFFFFu << (lane & 16);
    const bool P1 = (lane & 1) == 0;
    const bool P2 = (lane & 2) == 0;

    // ---- load: lane holds elements 4sh..4sh+3 = 3 x float4 ----
    const float* __restrict__ xrow = x + (size_t)row * 192;
    const float4* p4 = (const float4*)xrow + 3 * sh;
    float4 a = p4[0], b = p4[1], c = p4[2];

    // ---- squared norms, bit-matching ((x*x + y*y) + z*z) ----
    float n0 = __fadd_rn(__fadd_rn(__fmul_rn(a.x, a.x), __fmul_rn(a.y, a.y)), __fmul_rn(a.z, a.z));
    float n1 = __fadd_rn(__fadd_rn(__fmul_rn(a.w, a.w), __fmul_rn(b.x, b.x)), __fmul_rn(b.y, b.y));
    float n2 = __fadd_rn(__fadd_rn(__fmul_rn(b.z, b.z), __fmul_rn(b.w, b.w)), __fmul_rn(c.x, c.x));
    float n3 = __fadd_rn(__fadd_rn(__fmul_rn(c.y, c.y), __fmul_rn(c.z, c.z)), __fmul_rn(c.w, c.w));

    // ---- 32-bit keys: trunc26(norm) | (63 - idx), distinct -> total order ----
    const unsigned b63 = 63 - 4 * sh;
    unsigned K[4];
    K[0] = (__float_as_uint(n0) & 0xFFFFFFC0u) | (b63    );
    K[1] = (__float_as_uint(n1) & 0xFFFFFFC0u) | (b63 - 1);
    K[2] = (__float_as_uint(n2) & 0xFFFFFFC0u) | (b63 - 2);
    K[3] = (__float_as_uint(n3) & 0xFFFFFFC0u) | (b63 - 3);

    top16(K, P1, P2, 0xffffffffu);

    // ---- exactness check ----
    // t = full key at sorted position 15 (lane s4==3 of my group, reg 3)
    unsigned t = __shfl_sync(0xffffffffu, K[3], lane | 3);
    // (a) adjacent trunc-equal within top-16
    unsigned nk = __shfl_down_sync(0xffffffffu, K[0], 1);
    bool bad = (((K[0] ^ K[1]) >> 6) == 0) ||
               (((K[1] ^ K[2]) >> 6) == 0) ||
               (((K[2] ^ K[3]) >> 6) == 0) ||
               (((lane & 3) != 3) && (((K[3] ^ nk) >> 6) == 0));
    // (b) any original element trunc-equal to key15 but not key15 itself
    {
        unsigned o0 = (__float_as_uint(n0) & 0xFFFFFFC0u) | (b63    );
        unsigned o1 = (__float_as_uint(n1) & 0xFFFFFFC0u) | (b63 - 1);
        unsigned o2 = (__float_as_uint(n2) & 0xFFFFFFC0u) | (b63 - 2);
        unsigned o3 = (__float_as_uint(n3) & 0xFFFFFFC0u) | (b63 - 3);
        unsigned u0 = o0 ^ t, u1 = o1 ^ t, u2 = o2 ^ t, u3 = o3 ^ t;
        bad = bad || (u0 - 1u < 63u) || (u1 - 1u < 63u) || (u2 - 1u < 63u) || (u3 - 1u < 63u);
    }
    unsigned bal = __ballot_sync(0xffffffffu, bad);
    bool myHalfBad = ((bal >> (lane & 16)) & 0xFFFFu) != 0;

    float* __restrict__ orow = out + (size_t)row * 48;
    const int g2 = (lane >> 2) & 3;   // my reg for output
    const int s4 = lane & 3;
    const int p  = 4 * s4 + g2;       // my output position

    if (!myHalfBad) {
        unsigned t0 = (g2 & 1) ? K[1] : K[0];
        unsigned t1 = (g2 & 1) ? K[3] : K[2];
        unsigned Kp = (g2 & 2) ? t1 : t0;
        int idx = 63 - (int)(Kp & 63u);
        const float* v = xrow + 3 * idx;     // L1-resident re-read
        orow[3 * p + 0] = v[0];
        orow[3 * p + 1] = v[1];
        orow[3 * p + 2] = v[2];
    } else {
        // ---- exact fallback (rare, per-half-warp): 64-bit (norm, idx) keys, same network ----
        unsigned long long A[4];
        A[0] = ((unsigned long long)__float_as_uint(n0) << 32) | (b63    );
        A[1] = ((unsigned long long)__float_as_uint(n1) << 32) | (b63 - 1);
        A[2] = ((unsigned long long)__float_as_uint(n2) << 32) | (b63 - 2);
        A[3] = ((unsigned long long)__float_as_uint(n3) << 32) | (b63 - 3);
        top16(A, P1, P2, hm);
        unsigned long long t0 = (g2 & 1) ? A[1] : A[0];
        unsigned long long t1 = (g2 & 1) ? A[3] : A[2];
        unsigned long long Kp = (g2 & 2) ? t1 : t0;
        int idx = 63 - (int)(Kp & 63ull);
        const float* v = xrow + 3 * idx;
        orow[3 * p + 0] = v[0];
        orow[3 * p + 1] = v[1];
        orow[3 * p + 2] = v[2];
    }
}

extern "C" void kernel_launch(void* const* d_in, const int* in_sizes, int n_in,
                              void* d_out, int out_size) {
    const float* x = (const float*)d_in[0];
    float* out = (float*)d_out;
    vns_kernel<<<NROWS / ROWS_PER_BLOCK, TPB>>>(x, out);
}